// round 1
// baseline (speedup 1.0000x reference)
#include <cuda_runtime.h>
#include <cuda_bf16.h>
#include <cstdint>

#define EPS 1e-5f

// ---------------- device scratch (static allocation only) ----------------
__device__ float g_a1[64], g_b1[64], g_a2[64], g_b2[64];
__device__ float g_a3[2048], g_b3[2048];
__device__ unsigned long long g_w1pair[64 * 9];     // (s,s) packed f32x2, s = sign(conv1_w)
__device__ unsigned long long g_w2bits[64 * 9];     // conv2 sign bits over cin
__device__ unsigned long long g_fc1bits[2048 * 49]; // fc1 weights: word j packs channels c for index c*49+j
__device__ unsigned long long g_fc2bits[10 * 32];   // fc2 weights packed linearly
__device__ unsigned long long g_bits1[2048 * 14 * 14]; // block1 pooled sign bits (64 ch / word)
__device__ unsigned long long g_bits2[2048 * 7 * 7];   // block2 pooled sign bits
__device__ unsigned char      g_s3[2048 * 2048];       // fc1 sign bytes
__device__ unsigned long long g_bits3[2048 * 32];      // fc1 signs packed

// ---------------- packed f32x2 helpers ----------------
__device__ __forceinline__ unsigned long long fma2(unsigned long long a, unsigned long long b,
                                                   unsigned long long c) {
    unsigned long long d;
    asm("fma.rn.f32x2 %0, %1, %2, %3;" : "=l"(d) : "l"(a), "l"(b), "l"(c));
    return d;
}
__device__ __forceinline__ unsigned long long pack2(float lo, float hi) {
    unsigned long long d;
    asm("mov.b64 %0, {%1, %2};" : "=l"(d) : "f"(lo), "f"(hi));
    return d;
}
__device__ __forceinline__ void unpack2(unsigned long long v, float& lo, float& hi) {
    asm("mov.b64 {%0, %1}, %2;" : "=f"(lo), "=f"(hi) : "l"(v));
}

// ---------------- prep kernels ----------------
__global__ void prep_bn(const float* g1, const float* be1, const float* m1, const float* v1,
                        const float* g2, const float* be2, const float* m2, const float* v2,
                        const float* g3, const float* be3, const float* m3, const float* v3) {
    int i = blockIdx.x * blockDim.x + threadIdx.x;
    if (i < 64) {
        float a = g1[i] / sqrtf(v1[i] + EPS);
        g_a1[i] = a; g_b1[i] = be1[i] - m1[i] * a;
        float a2 = g2[i] / sqrtf(v2[i] + EPS);
        g_a2[i] = a2; g_b2[i] = be2[i] - m2[i] * a2;
    }
    if (i < 2048) {
        float a = g3[i] / sqrtf(v3[i] + EPS);
        g_a3[i] = a; g_b3[i] = be3[i] - m3[i] * a;
    }
}

__global__ void prep_w1(const float* w) {
    int i = blockIdx.x * blockDim.x + threadIdx.x;
    if (i < 576) {
        float s = (w[i] >= 0.0f) ? 1.0f : -1.0f;
        g_w1pair[i] = pack2(s, s);
    }
}

__global__ void prep_w2(const float* w) {
    int i = blockIdx.x * blockDim.x + threadIdx.x;
    if (i < 576) {
        int co = i / 9, t = i % 9;
        unsigned long long word = 0ULL;
        for (int cin = 0; cin < 64; cin++)
            if (w[co * 576 + cin * 9 + t] >= 0.0f) word |= 1ULL << cin;
        g_w2bits[i] = word;
    }
}

__global__ void prep_fc1(const float* w) {
    int o = blockIdx.x;       // 0..2047
    int j = threadIdx.x;      // 0..63 (guard at 49)
    if (j >= 49) return;
    unsigned long long word = 0ULL;
    const float* wo = w + o * 3136;
    for (int c = 0; c < 64; c++)
        if (wo[c * 49 + j] >= 0.0f) word |= 1ULL << c;
    g_fc1bits[o * 49 + j] = word;
}

__global__ void prep_fc2(const float* w) {
    int i = blockIdx.x * blockDim.x + threadIdx.x;
    if (i < 320) {
        int o = i / 32, j = i % 32;
        unsigned long long word = 0ULL;
        const float* wo = w + o * 2048 + j * 64;
        for (int r = 0; r < 64; r++)
            if (wo[r] >= 0.0f) word |= 1ULL << r;
        g_fc2bits[i] = word;
    }
}

// ---------------- conv1 + bn1 + sign + maxpool (fused) ----------------
// one thread per pooled pixel (b, py, px); computes all 64 channels,
// 2 sub-positions per packed fma.rn.f32x2.
__global__ void conv1_kernel(const float* __restrict__ x) {
    __shared__ unsigned long long sw[576];
    __shared__ float sa[64], sb[64];
    int tid = threadIdx.x;
    for (int i = tid; i < 576; i += blockDim.x) sw[i] = g_w1pair[i];
    if (tid < 64) { sa[tid] = g_a1[tid]; sb[tid] = g_b1[tid]; }
    __syncthreads();

    int idx = blockIdx.x * blockDim.x + tid;
    if (idx >= 2048 * 196) return;
    int b = idx / 196, p = idx % 196;
    int py = p / 14, px = p % 14;
    const float* xb = x + b * 784;

    float pix[16];
#pragma unroll
    for (int i = 0; i < 4; i++) {
        int r = 2 * py - 1 + i; r = min(max(r, 0), 27);
#pragma unroll
        for (int j = 0; j < 4; j++) {
            int c = 2 * px - 1 + j; c = min(max(c, 0), 27);
            pix[i * 4 + j] = xb[r * 28 + c];
        }
    }
    // packed pixel pairs: pp[dy][tap] = (pix for dx=0, pix for dx=1)
    unsigned long long pp[2][9];
#pragma unroll
    for (int dy = 0; dy < 2; dy++)
#pragma unroll
        for (int ky = 0; ky < 3; ky++)
#pragma unroll
            for (int kx = 0; kx < 3; kx++)
                pp[dy][ky * 3 + kx] =
                    pack2(pix[(dy + ky) * 4 + kx], pix[(dy + ky) * 4 + kx + 1]);

    unsigned long long word = 0ULL;
    for (int co = 0; co < 64; co++) {
        unsigned long long acc0 = 0ULL, acc1 = 0ULL; // (0.0f, 0.0f)
#pragma unroll
        for (int t = 0; t < 9; t++) {
            unsigned long long w = sw[co * 9 + t];
            acc0 = fma2(w, pp[0][t], acc0);
            acc1 = fma2(w, pp[1][t], acc1);
        }
        float v00, v01, v10, v11;
        unpack2(acc0, v00, v01);
        unpack2(acc1, v10, v11);
        float m = fmaxf(fmaxf(v00, v01), fmaxf(v10, v11));
        // a >= 0 (gamma uniform[0,1)) -> pooled sign = sign(a*max + b)
        if (fmaf(sa[co], m, sb[co]) >= 0.0f) word |= 1ULL << co;
    }
    g_bits1[b * 196 + py * 14 + px] = word;
}

// ---------------- conv2 + bn2 + sign + maxpool (XNOR-popcount, fused) ----------------
__global__ void conv2_kernel() {
    __shared__ unsigned long long sw[576];
    __shared__ float sa[64], sb[64];
    int tid = threadIdx.x;
    for (int i = tid; i < 576; i += blockDim.x) sw[i] = g_w2bits[i];
    if (tid < 64) { sa[tid] = g_a2[tid]; sb[tid] = g_b2[tid]; }
    __syncthreads();

    int idx = blockIdx.x * blockDim.x + tid;
    if (idx >= 2048 * 49) return;
    int b = idx / 49, p = idx % 49;
    int py = p / 7, px = p % 7;
    const unsigned long long* ib = g_bits1 + b * 196;

    unsigned long long pix[16];
#pragma unroll
    for (int i = 0; i < 4; i++) {
        int r = 2 * py - 1 + i; r = min(max(r, 0), 13);
#pragma unroll
        for (int j = 0; j < 4; j++) {
            int c = 2 * px - 1 + j; c = min(max(c, 0), 13);
            pix[i * 4 + j] = ib[r * 14 + c];
        }
    }

    unsigned long long word = 0ULL;
    for (int co = 0; co < 64; co++) {
        unsigned long long wreg[9];
#pragma unroll
        for (int t = 0; t < 9; t++) wreg[t] = sw[co * 9 + t];
        int smin = 1 << 30; // dot = 576 - 2*s  ->  max dot = min s
#pragma unroll
        for (int dy = 0; dy < 2; dy++)
#pragma unroll
            for (int dx = 0; dx < 2; dx++) {
                int s = 0;
#pragma unroll
                for (int ky = 0; ky < 3; ky++)
#pragma unroll
                    for (int kx = 0; kx < 3; kx++)
                        s += __popcll(pix[(dy + ky) * 4 + (dx + kx)] ^ wreg[ky * 3 + kx]);
                smin = min(smin, s);
            }
        float d = (float)(576 - 2 * smin);
        if (fmaf(sa[co], d, sb[co]) >= 0.0f) word |= 1ULL << co;
    }
    g_bits2[b * 49 + p] = word;
}

// ---------------- fc1: 2048x2048 XNOR GEMM, K = 49 u64 words ----------------
// 64x64 tile, 256 threads, 16 outputs/thread, K split 25/24 to fit smem.
__global__ void fc1_kernel() {
    __shared__ unsigned long long sA[64][25];
    __shared__ unsigned long long sB[64][25];
    int tid = threadIdx.x;
    int tx = tid & 15, ty = tid >> 4;
    int b0 = blockIdx.y * 64;
    int n0 = blockIdx.x * 64;

    int acc[4][4];
#pragma unroll
    for (int i = 0; i < 4; i++)
#pragma unroll
        for (int j = 0; j < 4; j++) acc[i][j] = 0;

    for (int ph = 0; ph < 2; ph++) {
        int k0 = ph * 25;
        int kn = ph ? 24 : 25;
        __syncthreads();
        for (int e = tid; e < 64 * kn; e += 256) {
            int r = e / kn, kk = e % kn;
            sA[r][kk] = g_bits2[(b0 + r) * 49 + k0 + kk];
            sB[r][kk] = g_fc1bits[(n0 + r) * 49 + k0 + kk];
        }
        __syncthreads();
        for (int kk = 0; kk < kn; kk++) {
            unsigned long long a0 = sA[ty][kk],      a1 = sA[ty + 16][kk],
                               a2 = sA[ty + 32][kk], a3v = sA[ty + 48][kk];
            unsigned long long bw0 = sB[tx][kk],      bw1 = sB[tx + 16][kk],
                               bw2 = sB[tx + 32][kk], bw3 = sB[tx + 48][kk];
            acc[0][0] += __popcll(a0 ^ bw0);  acc[0][1] += __popcll(a0 ^ bw1);
            acc[0][2] += __popcll(a0 ^ bw2);  acc[0][3] += __popcll(a0 ^ bw3);
            acc[1][0] += __popcll(a1 ^ bw0);  acc[1][1] += __popcll(a1 ^ bw1);
            acc[1][2] += __popcll(a1 ^ bw2);  acc[1][3] += __popcll(a1 ^ bw3);
            acc[2][0] += __popcll(a2 ^ bw0);  acc[2][1] += __popcll(a2 ^ bw1);
            acc[2][2] += __popcll(a2 ^ bw2);  acc[2][3] += __popcll(a2 ^ bw3);
            acc[3][0] += __popcll(a3v ^ bw0); acc[3][1] += __popcll(a3v ^ bw1);
            acc[3][2] += __popcll(a3v ^ bw2); acc[3][3] += __popcll(a3v ^ bw3);
        }
    }

#pragma unroll
    for (int i = 0; i < 4; i++) {
        int gr = b0 + ty + 16 * i;
#pragma unroll
        for (int j = 0; j < 4; j++) {
            int gc = n0 + tx + 16 * j;
            float d = (float)(3136 - 2 * acc[i][j]);
            g_s3[gr * 2048 + gc] = (fmaf(g_a3[gc], d, g_b3[gc]) >= 0.0f) ? 1 : 0;
        }
    }
}

// ---------------- pack fc1 sign bytes into bit words ----------------
__global__ void pack3_kernel() {
    int idx = blockIdx.x * blockDim.x + threadIdx.x;
    if (idx >= 2048 * 32) return;
    int b = idx >> 5, j = idx & 31;
    const unsigned char* s = g_s3 + b * 2048 + j * 64;
    unsigned long long w = 0ULL;
#pragma unroll 8
    for (int r = 0; r < 64; r++)
        w |= (unsigned long long)(s[r] & 1) << r;
    g_bits3[idx] = w;
}

// ---------------- fc2: [2048,2048] x [10,2048] XNOR GEMM + scale ----------------
__global__ void fc2_kernel(float* __restrict__ out, const float* __restrict__ scale) {
    int idx = blockIdx.x * blockDim.x + threadIdx.x;
    if (idx >= 2048 * 10) return;
    int b = idx / 10, o = idx % 10;
    const unsigned long long* xb = g_bits3 + b * 32;
    const unsigned long long* wb = g_fc2bits + o * 32;
    int s = 0;
#pragma unroll
    for (int j = 0; j < 32; j++) s += __popcll(xb[j] ^ wb[j]);
    out[idx] = scale[0] * (float)(2048 - 2 * s);
}

// ---------------- launch ----------------
extern "C" void kernel_launch(void* const* d_in, const int* in_sizes, int n_in,
                              void* d_out, int out_size) {
    const float* x       = (const float*)d_in[0];
    const float* conv1_w = (const float*)d_in[1];
    const float* bn1_g   = (const float*)d_in[2];
    const float* bn1_b   = (const float*)d_in[3];
    const float* bn1_m   = (const float*)d_in[4];
    const float* bn1_v   = (const float*)d_in[5];
    const float* conv2_w = (const float*)d_in[6];
    const float* bn2_g   = (const float*)d_in[7];
    const float* bn2_b   = (const float*)d_in[8];
    const float* bn2_m   = (const float*)d_in[9];
    const float* bn2_v   = (const float*)d_in[10];
    const float* fc1_w   = (const float*)d_in[11];
    const float* bn3_g   = (const float*)d_in[12];
    const float* bn3_b   = (const float*)d_in[13];
    const float* bn3_m   = (const float*)d_in[14];
    const float* bn3_v   = (const float*)d_in[15];
    const float* fc2_w   = (const float*)d_in[16];
    const float* scale   = (const float*)d_in[17];
    float* out = (float*)d_out;

    prep_bn<<<8, 256>>>(bn1_g, bn1_b, bn1_m, bn1_v,
                        bn2_g, bn2_b, bn2_m, bn2_v,
                        bn3_g, bn3_b, bn3_m, bn3_v);
    prep_w1<<<3, 256>>>(conv1_w);
    prep_w2<<<3, 256>>>(conv2_w);
    prep_fc1<<<2048, 64>>>(fc1_w);
    prep_fc2<<<2, 256>>>(fc2_w);

    conv1_kernel<<<(2048 * 196 + 255) / 256, 256>>>(x);
    conv2_kernel<<<(2048 * 49 + 127) / 128, 128>>>();
    fc1_kernel<<<dim3(32, 32), 256>>>();
    pack3_kernel<<<(2048 * 32 + 255) / 256, 256>>>();
    fc2_kernel<<<(2048 * 10 + 255) / 256, 256>>>(out, scale);
}